// round 13
// baseline (speedup 1.0000x reference)
#include <cuda_runtime.h>
#include <cstdint>

#define LC 1024
#define CS 768
#define NH 16
#define DH 48
#define CP 128

typedef unsigned long long ull;
typedef unsigned int u32;

// ---- scratch (device globals) ----
__device__ float g_Q[LC * CS];
__device__ float g_K[LC * CS];
__device__ float g_V[LC * CS];
__device__ float g_gate[LC * CS];
__device__ float g_ctx[LC * CS];
__device__ float g_attn_fallback[NH * LC * LC];
__device__ int   g_mask_is_u8;

// ---- f32x2 helpers ----
__device__ __forceinline__ ull ffma2(ull a, ull b, ull c) {
    ull d;
    asm("fma.rn.f32x2 %0,%1,%2,%3;" : "=l"(d) : "l"(a), "l"(b), "l"(c));
    return d;
}
__device__ __forceinline__ ull pack2(float lo, float hi) {
    ull r;
    asm("mov.b64 %0,{%1,%2};" : "=l"(r) : "f"(lo), "f"(hi));
    return r;
}
__device__ __forceinline__ void unpack2(ull v, float& lo, float& hi) {
    asm("mov.b64 {%0,%1},%2;" : "=f"(lo), "=f"(hi) : "l"(v));
}

// ---- tf32 mma helpers ----
__device__ __forceinline__ unsigned f2tf(float x) {
    unsigned r;
    asm("cvt.rna.tf32.f32 %0, %1;" : "=r"(r) : "f"(x));
    return r;
}
__device__ __forceinline__ void split_tf32(float x, unsigned& h, unsigned& l) {
    h = f2tf(x);
    l = f2tf(x - __uint_as_float(h));
}
__device__ __forceinline__ void mma_tf32(float* c, const unsigned* a, const unsigned* b) {
    asm("mma.sync.aligned.m16n8k8.row.col.f32.tf32.tf32.f32 "
        "{%0,%1,%2,%3}, {%4,%5,%6,%7}, {%8,%9}, {%0,%1,%2,%3};"
        : "+f"(c[0]), "+f"(c[1]), "+f"(c[2]), "+f"(c[3])
        : "r"(a[0]), "r"(a[1]), "r"(a[2]), "r"(a[3]), "r"(b[0]), "r"(b[1]));
}

// ---- FMA-pipe exp (no MUFU): range-reduce + Taylor-5, rel err ~2e-6 ----
__device__ __forceinline__ float fexp(float x) {
    x = fmaxf(x, -80.f);                       // masked -1e30 -> ~0 safely
    float zf = fmaf(x, 1.44269504089f, 12582912.f);   // round(x/ln2) in mantissa
    int   ii = __float_as_int(zf) - 0x4B400000;
    float fi = zf - 12582912.f;
    float f  = fmaf(-fi, 0.693359375f, x);            // x - i*ln2 (hi)
    f        = fmaf(-fi, -2.12194440e-4f, f);         // ... (lo)
    float p  = 8.3333333e-3f;                          // 1/120
    p = fmaf(p, f, 4.1666667e-2f);                     // 1/24
    p = fmaf(p, f, 1.6666667e-1f);                     // 1/6
    p = fmaf(p, f, 5.0e-1f);
    p = fmaf(p, f, 1.f);
    p = fmaf(p, f, 1.f);
    return __int_as_float(__float_as_int(p) + (ii << 23));
}

// =====================================================================
// K0: mask dtype detector
// =====================================================================
__global__ void k_detect(const unsigned int* __restrict__ m)
{
    __shared__ int s;
    if (threadIdx.x == 0) s = 0;
    __syncthreads();
    int bad = 0;
    for (int i = threadIdx.x; i < 1024; i += blockDim.x)
        if (m[i] > 1u) bad = 1;
    if (bad) atomicOr(&s, 1);
    __syncthreads();
    if (threadIdx.x == 0) g_mask_is_u8 = s;
}

// =====================================================================
// K1: fused projections via tensor cores (tf32x3, inline split)
// =====================================================================
__global__ void __launch_bounds__(256) k_proj_tc(
    const float* __restrict__ S,
    const float* __restrict__ Wq, const float* __restrict__ bq,
    const float* __restrict__ Wk, const float* __restrict__ bk,
    const float* __restrict__ Wv, const float* __restrict__ bv,
    const float* __restrict__ Wg, const float* __restrict__ bg)
{
    __shared__ __align__(16) float As[128 * 36];
    __shared__ __align__(16) float Bs[64 * 36];

    int ntb = blockIdx.x;
    int wi = ntb / 12;
    int n0 = (ntb % 12) * 64;
    int m0 = blockIdx.y * 128;

    const float* W   = wi == 0 ? Wq : wi == 1 ? Wk : wi == 2 ? Wv : Wg;
    const float* bb  = wi == 0 ? bq : wi == 1 ? bk : wi == 2 ? bv : bg;
    float*       dst = wi == 0 ? g_Q : wi == 1 ? g_K : wi == 2 ? g_V : g_gate;

    int t = threadIdx.x;
    int warp = t >> 5, lane = t & 31;
    int wm = warp >> 1, wn = warp & 1;
    int g = lane >> 2, tg = lane & 3;

    float acc[2][4][4] = {};

    for (int k0 = 0; k0 < CS; k0 += 32) {
#pragma unroll
        for (int l = 0; l < 4; l++) {
            int idx = l * 256 + t, row = idx >> 3, q = idx & 7;
            float4 v = *(const float4*)(S + (size_t)(m0 + row) * CS + k0 + q * 4);
            *(float4*)(As + row * 36 + q * 4) = v;
        }
#pragma unroll
        for (int l = 0; l < 2; l++) {
            int idx = l * 256 + t, kk = idx >> 4, q = idx & 15;
            float4 v = *(const float4*)(W + (size_t)(k0 + kk) * CS + n0 + q * 4);
            Bs[(q * 4 + 0) * 36 + kk] = v.x;
            Bs[(q * 4 + 1) * 36 + kk] = v.y;
            Bs[(q * 4 + 2) * 36 + kk] = v.z;
            Bs[(q * 4 + 3) * 36 + kk] = v.w;
        }
        __syncthreads();

#pragma unroll
        for (int ks = 0; ks < 4; ks++) {
            int kb = ks * 8;
            unsigned bh[4][2], bl[4][2];
#pragma unroll
            for (int nt = 0; nt < 4; nt++)
#pragma unroll
                for (int e = 0; e < 2; e++)
                    split_tf32(Bs[(wn * 32 + nt * 8 + g) * 36 + kb + tg + 4 * e],
                               bh[nt][e], bl[nt][e]);
#pragma unroll
            for (int mt = 0; mt < 2; mt++) {
                unsigned ah[4], al[4];
                int r0 = wm * 32 + mt * 16 + g;
                split_tf32(As[r0 * 36 + kb + tg],           ah[0], al[0]);
                split_tf32(As[(r0 + 8) * 36 + kb + tg],     ah[1], al[1]);
                split_tf32(As[r0 * 36 + kb + tg + 4],       ah[2], al[2]);
                split_tf32(As[(r0 + 8) * 36 + kb + tg + 4], ah[3], al[3]);
#pragma unroll
                for (int nt = 0; nt < 4; nt++) {
                    mma_tf32(acc[mt][nt], ah, bh[nt]);
                    mma_tf32(acc[mt][nt], ah, bl[nt]);
                    mma_tf32(acc[mt][nt], al, bh[nt]);
                }
            }
        }
        __syncthreads();
    }

#pragma unroll
    for (int mt = 0; mt < 2; mt++)
#pragma unroll
        for (int nt = 0; nt < 4; nt++) {
            int col = n0 + wn * 32 + nt * 8 + 2 * tg;
            float b0 = bb[col], b1 = bb[col + 1];
            int r = m0 + wm * 32 + mt * 16 + g;
            float v0 = acc[mt][nt][0] + b0, v1 = acc[mt][nt][1] + b1;
            float v2 = acc[mt][nt][2] + b0, v3 = acc[mt][nt][3] + b1;
            if (wi == 3) {
                v0 = 1.f / (1.f + __expf(-v0));
                v1 = 1.f / (1.f + __expf(-v1));
                v2 = 1.f / (1.f + __expf(-v2));
                v3 = 1.f / (1.f + __expf(-v3));
            }
            *(float2*)(dst + (size_t)r * CS + col)       = make_float2(v0, v1);
            *(float2*)(dst + (size_t)(r + 8) * CS + col) = make_float2(v2, v3);
        }
}

// =====================================================================
// K2: pair bias via TC, raw-bit tf32 z, K chunked (2x64), 4 CTAs/SM
// =====================================================================
#define ZP  132
#define ZP2 68
#define CBP 18

__global__ void __launch_bounds__(256) k_pairbias_tc(
    const float* __restrict__ z, const void* __restrict__ maskp,
    const float* __restrict__ dist, const float* __restrict__ prior,
    const float* __restrict__ Wz, float* __restrict__ A)
{
    extern __shared__ __align__(16) u32 smp[];
    u32*   Zs   = smp;                           // 128*68 chunk (raw fp32 bits)
    u32*   Wzs  = smp + 128 * ZP2;               // 16*132 tf32 full K
    float* Cbuf = (float*)(Wzs + 16 * ZP);       // 128*18
    float* tr   = (float*)smp;                   // reuse Zs after mma

    int i = blockIdx.x, jt = blockIdx.y;
    int t = threadIdx.x;
    int warp = t >> 5, lane = t & 31;
    int g = lane >> 2, tg = lane & 3;

#pragma unroll
    for (int l = 0; l < 8; l++) {
        int idx = l * 256 + t;
        int c = idx >> 4, h = idx & 15;
        Wzs[h * ZP + c] = f2tf(Wz[c * 16 + h]);
    }

    float acc[2][4] = {};
    int p0 = warp * 16 + g;

#pragma unroll
    for (int ch = 0; ch < 2; ch++) {
        const uint4* zb = (const uint4*)(z + ((size_t)i * LC + jt * 128) * CP + ch * 64);
#pragma unroll
        for (int l = 0; l < 8; l++) {
            int idx = l * 256 + t;
            int pair = idx >> 4, q = idx & 15;
            *(uint4*)(Zs + pair * ZP2 + q * 4) = zb[pair * 32 + q];
        }
        __syncthreads();

#pragma unroll
        for (int ks = 0; ks < 8; ks++) {
            int kb = ks * 8;
            unsigned a[4];
            a[0] = Zs[p0 * ZP2 + kb + tg];
            a[1] = Zs[(p0 + 8) * ZP2 + kb + tg];
            a[2] = Zs[p0 * ZP2 + kb + tg + 4];
            a[3] = Zs[(p0 + 8) * ZP2 + kb + tg + 4];
#pragma unroll
            for (int nt = 0; nt < 2; nt++) {
                unsigned b[2];
                b[0] = Wzs[(nt * 8 + g) * ZP + ch * 64 + kb + tg];
                b[1] = Wzs[(nt * 8 + g) * ZP + ch * 64 + kb + tg + 4];
                mma_tf32(acc[nt], a, b);
            }
        }
        __syncthreads();
    }

#pragma unroll
    for (int nt = 0; nt < 2; nt++) {
        int h0 = nt * 8 + 2 * tg;
        Cbuf[p0 * CBP + h0]           = acc[nt][0];
        Cbuf[p0 * CBP + h0 + 1]       = acc[nt][1];
        Cbuf[(p0 + 8) * CBP + h0]     = acc[nt][2];
        Cbuf[(p0 + 8) * CBP + h0 + 1] = acc[nt][3];
    }
    __syncthreads();

    float v16[16];
    if (t < 128) {
        int j = jt * 128 + t;
        int ij = i * LC + j;
        const float4* dv = (const float4*)(dist + (size_t)ij * 16);
        float4 d0 = dv[0], d1 = dv[1], d2 = dv[2], d3 = dv[3];
        float db[16] = {d0.x, d0.y, d0.z, d0.w, d1.x, d1.y, d1.z, d1.w,
                        d2.x, d2.y, d2.z, d2.w, d3.x, d3.y, d3.z, d3.w};
        float pr = prior[ij];
        bool mv;
        if (g_mask_is_u8)
            mv = ((const unsigned char*)maskp)[ij] != 0;
        else
            mv = ((const int*)maskp)[ij] != 0;
#pragma unroll
        for (int hh = 0; hh < 16; hh++) {
            float vv = Cbuf[t * CBP + hh] + db[hh] + pr;
            v16[hh] = mv ? vv : -1e30f;
        }
    }
    __syncthreads();
    if (t < 128) {
#pragma unroll
        for (int hh = 0; hh < 16; hh++) tr[hh * 128 + t] = v16[hh];
    }
    __syncthreads();
#pragma unroll
    for (int l = 0; l < 8; l++) {
        int idx = l * 256 + t;
        int hh = idx >> 7, col = idx & 127;
        A[((size_t)hh * LC + i) * LC + jt * 128 + col] = tr[hh * 128 + col];
    }
}

// =====================================================================
// K3: logits += scale*QK^T, k-paired f32x2 (RMW)
// =====================================================================
#define QK_SCALE 0.14433756729740643f   // 1/sqrt(48)

__global__ void __launch_bounds__(256, 2) k_qk(float* __restrict__ A)
{
    __shared__ __align__(16) ull Asp[24 * 128];
    __shared__ __align__(16) ull Bsp[24 * 64];

    int jb = blockIdx.x;
    int j0 = jb * 64, i0 = blockIdx.y * 128, h = blockIdx.z;
    int t = threadIdx.x, tx = t & 15, ty = t >> 4;

#pragma unroll
    for (int l = 0; l < 6; l++) {
        int idx = l * 256 + t;
        int row = idx & 127, q = idx >> 7;
        float4 v = *(const float4*)(g_Q + (size_t)(i0 + row) * CS + h * DH + q * 4);
        Asp[(2 * q) * 128 + row]     = pack2(v.x * QK_SCALE, v.y * QK_SCALE);
        Asp[(2 * q + 1) * 128 + row] = pack2(v.z * QK_SCALE, v.w * QK_SCALE);
    }
#pragma unroll
    for (int l = 0; l < 3; l++) {
        int idx = l * 256 + t;
        int row = idx & 63, q = idx >> 6;
        float4 v = *(const float4*)(g_K + (size_t)(j0 + row) * CS + h * DH + q * 4);
        Bsp[(2 * q) * 64 + row]     = pack2(v.x, v.y);
        Bsp[(2 * q + 1) * 64 + row] = pack2(v.z, v.w);
    }
    __syncthreads();

    ull acc[8][4];
#pragma unroll
    for (int r = 0; r < 8; r++)
#pragma unroll
        for (int j = 0; j < 4; j++) acc[r][j] = 0ull;

#pragma unroll 6
    for (int kp = 0; kp < 24; kp++) {
        const ulonglong2* Ap2 = (const ulonglong2*)(Asp + kp * 128);
        const ull* Bp = Bsp + kp * 64;
        ull b[4];
#pragma unroll
        for (int j = 0; j < 4; j++) b[j] = Bp[tx + 16 * j];
#pragma unroll
        for (int p = 0; p < 4; p++) {
            ulonglong2 av = Ap2[ty * 4 + p];
#pragma unroll
            for (int j = 0; j < 4; j++) {
                acc[2 * p][j]     = ffma2(av.x, b[j], acc[2 * p][j]);
                acc[2 * p + 1][j] = ffma2(av.y, b[j], acc[2 * p + 1][j]);
            }
        }
    }

#pragma unroll
    for (int r = 0; r < 8; r++) {
        int row = i0 + ty * 8 + r;
        float* C = A + ((size_t)h * LC + row) * LC + j0;
#pragma unroll
        for (int j = 0; j < 4; j++) {
            float lo, hi;
            unpack2(acc[r][j], lo, hi);
            C[tx + 16 * j] += lo + hi;
        }
    }
}

// =====================================================================
// K3b: rowwise softmax, HYBRID exp: 4 elems MUFU (__expf) + 4 elems
// FMA-pipe polynomial (fexp) per thread -> ~2x exp throughput
// =====================================================================
__global__ void __launch_bounds__(128) k_softmax(float* __restrict__ A)
{
    size_t r = blockIdx.x;
    float* row = A + r * LC;
    int t = threadIdx.x;
    float4 v0 = ((float4*)row)[2 * t], v1 = ((float4*)row)[2 * t + 1];

    float mx = fmaxf(fmaxf(fmaxf(v0.x, v0.y), fmaxf(v0.z, v0.w)),
                     fmaxf(fmaxf(v1.x, v1.y), fmaxf(v1.z, v1.w)));
#pragma unroll
    for (int o = 16; o; o >>= 1) mx = fmaxf(mx, __shfl_xor_sync(0xffffffffu, mx, o));
    __shared__ float sm[4], ss[4];
    if ((t & 31) == 0) sm[t >> 5] = mx;
    __syncthreads();
    mx = fmaxf(fmaxf(sm[0], sm[1]), fmaxf(sm[2], sm[3]));

    // interleave MUFU and FMA-pipe exps so both pipes fill concurrently
    v0.x = __expf(v0.x - mx);
    v1.x = fexp(v1.x - mx);
    v0.y = __expf(v0.y - mx);
    v1.y = fexp(v1.y - mx);
    v0.z = __expf(v0.z - mx);
    v1.z = fexp(v1.z - mx);
    v0.w = __expf(v0.w - mx);
    v1.w = fexp(v1.w - mx);

    float s = v0.x + v0.y + v0.z + v0.w + v1.x + v1.y + v1.z + v1.w;
#pragma unroll
    for (int o = 16; o; o >>= 1) s += __shfl_xor_sync(0xffffffffu, s, o);
    if ((t & 31) == 0) ss[t >> 5] = s;
    __syncthreads();
    s = ss[0] + ss[1] + ss[2] + ss[3];

    float inv = 1.f / s;
    v0.x *= inv; v0.y *= inv; v0.z *= inv; v0.w *= inv;
    v1.x *= inv; v1.y *= inv; v1.z *= inv; v1.w *= inv;
    ((float4*)row)[2 * t] = v0;
    ((float4*)row)[2 * t + 1] = v1;
}

// =====================================================================
// K4: ctx = attn @ V per head. tile 64 rows, 128 thr, micro 8x3 (f32x2)
// =====================================================================
__global__ void __launch_bounds__(128) k_av(const float* __restrict__ A)
{
    __shared__ __align__(16) float  As[32 * 64];
    __shared__ __align__(16) float2 Vs[32 * 48];

    int i0 = blockIdx.x * 64, h = blockIdx.y;
    int t = threadIdx.x, tx = t & 15, ty = t >> 4;

    ull acc[4][3];
#pragma unroll
    for (int p = 0; p < 4; p++)
#pragma unroll
        for (int c = 0; c < 3; c++) acc[p][c] = 0ull;

    for (int j0 = 0; j0 < LC; j0 += 32) {
#pragma unroll
        for (int l = 0; l < 4; l++) {
            int idx = l * 128 + t, row = idx >> 3, q = idx & 7;
            float4 v = *(const float4*)(A + ((size_t)h * LC + i0 + row) * LC + j0 + q * 4);
            As[(q * 4 + 0) * 64 + row] = v.x;
            As[(q * 4 + 1) * 64 + row] = v.y;
            As[(q * 4 + 2) * 64 + row] = v.z;
            As[(q * 4 + 3) * 64 + row] = v.w;
        }
#pragma unroll
        for (int l = 0; l < 3; l++) {
            int idx = l * 128 + t;
            int jj = idx / 12, q = idx - jj * 12;
            float4 v = *(const float4*)(g_V + (size_t)(j0 + jj) * CS + h * DH + q * 4);
            Vs[jj * 48 + q * 4 + 0] = make_float2(v.x, v.x);
            Vs[jj * 48 + q * 4 + 1] = make_float2(v.y, v.y);
            Vs[jj * 48 + q * 4 + 2] = make_float2(v.z, v.z);
            Vs[jj * 48 + q * 4 + 3] = make_float2(v.w, v.w);
        }
        __syncthreads();
#pragma unroll
        for (int kk = 0; kk < 32; kk++) {
            const ull* Ap = (const ull*)(As + kk * 64);
            const ull* Vp = (const ull*)(Vs + kk * 48);
            ull a2[4], b2[3];
#pragma unroll
            for (int p = 0; p < 4; p++) a2[p] = Ap[ty * 4 + p];
#pragma unroll
            for (int c = 0; c < 3; c++) b2[c] = Vp[tx * 3 + c];
#pragma unroll
            for (int p = 0; p < 4; p++)
#pragma unroll
                for (int c = 0; c < 3; c++) acc[p][c] = ffma2(a2[p], b2[c], acc[p][c]);
        }
        __syncthreads();
    }

#pragma unroll
    for (int p = 0; p < 4; p++) {
        int r = i0 + ty * 8 + 2 * p;
#pragma unroll
        for (int c = 0; c < 3; c++) {
            float lo, hi;
            unpack2(acc[p][c], lo, hi);
            g_ctx[(size_t)r * CS + h * DH + tx * 3 + c]       = lo;
            g_ctx[(size_t)(r + 1) * CS + h * DH + tx * 3 + c] = hi;
        }
    }
}

// =====================================================================
// K5: y = gate * (ctx @ Wo + bo) via tensor cores (tf32x3, inline split)
// =====================================================================
__global__ void __launch_bounds__(256) k_out_tc(
    const float* __restrict__ Wo, const float* __restrict__ bo, float* __restrict__ Y)
{
    __shared__ __align__(16) float As[128 * 36];
    __shared__ __align__(16) float Bs[64 * 36];

    int n0 = blockIdx.x * 64;
    int m0 = blockIdx.y * 128;

    int t = threadIdx.x;
    int warp = t >> 5, lane = t & 31;
    int wm = warp >> 1, wn = warp & 1;
    int g = lane >> 2, tg = lane & 3;

    float acc[2][4][4] = {};

    for (int k0 = 0; k0 < CS; k0 += 32) {
#pragma unroll
        for (int l = 0; l < 4; l++) {
            int idx = l * 256 + t, row = idx >> 3, q = idx & 7;
            float4 v = *(const float4*)(g_ctx + (size_t)(m0 + row) * CS + k0 + q * 4);
            *(float4*)(As + row * 36 + q * 4) = v;
        }
#pragma unroll
        for (int l = 0; l < 2; l++) {
            int idx = l * 256 + t, kk = idx >> 4, q = idx & 15;
            float4 v = *(const float4*)(Wo + (size_t)(k0 + kk) * CS + n0 + q * 4);
            Bs[(q * 4 + 0) * 36 + kk] = v.x;
            Bs[(q * 4 + 1) * 36 + kk] = v.y;
            Bs[(q * 4 + 2) * 36 + kk] = v.z;
            Bs[(q * 4 + 3) * 36 + kk] = v.w;
        }
        __syncthreads();

#pragma unroll
        for (int ks = 0; ks < 4; ks++) {
            int kb = ks * 8;
            unsigned bh[4][2], bl[4][2];
#pragma unroll
            for (int nt = 0; nt < 4; nt++)
#pragma unroll
                for (int e = 0; e < 2; e++)
                    split_tf32(Bs[(wn * 32 + nt * 8 + g) * 36 + kb + tg + 4 * e],
                               bh[nt][e], bl[nt][e]);
#pragma unroll
            for (int mt = 0; mt < 2; mt++) {
                unsigned ah[4], al[4];
                int r0 = wm * 32 + mt * 16 + g;
                split_tf32(As[r0 * 36 + kb + tg],           ah[0], al[0]);
                split_tf32(As[(r0 + 8) * 36 + kb + tg],     ah[1], al[1]);
                split_tf32(As[r0 * 36 + kb + tg + 4],       ah[2], al[2]);
                split_tf32(As[(r0 + 8) * 36 + kb + tg + 4], ah[3], al[3]);
#pragma unroll
                for (int nt = 0; nt < 4; nt++) {
                    mma_tf32(acc[mt][nt], ah, bh[nt]);
                    mma_tf32(acc[mt][nt], ah, bl[nt]);
                    mma_tf32(acc[mt][nt], al, bh[nt]);
                }
            }
        }
        __syncthreads();
    }

#pragma unroll
    for (int mt = 0; mt < 2; mt++)
#pragma unroll
        for (int nt = 0; nt < 4; nt++) {
            int col = n0 + wn * 32 + nt * 8 + 2 * tg;
            float b0 = bo[col], b1 = bo[col + 1];
            int r = m0 + wm * 32 + mt * 16 + g;
            float2 ga = *(const float2*)(g_gate + (size_t)r * CS + col);
            float2 gb = *(const float2*)(g_gate + (size_t)(r + 8) * CS + col);
            *(float2*)(Y + (size_t)r * CS + col) =
                make_float2((acc[mt][nt][0] + b0) * ga.x, (acc[mt][nt][1] + b1) * ga.y);
            *(float2*)(Y + (size_t)(r + 8) * CS + col) =
                make_float2((acc[mt][nt][2] + b0) * gb.x, (acc[mt][nt][3] + b1) * gb.y);
        }
}

// =====================================================================
extern "C" void kernel_launch(void* const* d_in, const int* in_sizes, int n_in,
                              void* d_out, int out_size)
{
    const float* s     = (const float*)d_in[0];
    const float* z     = (const float*)d_in[1];
    const void*  mask  = d_in[2];
    const float* dist  = (const float*)d_in[3];
    const float* prior = (const float*)d_in[4];
    const float* Wq = (const float*)d_in[5];  const float* bq = (const float*)d_in[6];
    const float* Wk = (const float*)d_in[7];  const float* bk = (const float*)d_in[8];
    const float* Wv = (const float*)d_in[9];  const float* bv = (const float*)d_in[10];
    const float* Wz = (const float*)d_in[11];
    const float* Wo = (const float*)d_in[12]; const float* bo = (const float*)d_in[13];
    const float* Wg = (const float*)d_in[14]; const float* bg = (const float*)d_in[15];

    float* Y = (float*)d_out;
    float* attn;
    if (out_size >= LC * CS + NH * LC * LC) {
        attn = (float*)d_out + LC * CS;
    } else {
        void* p = nullptr;
        cudaGetSymbolAddress(&p, g_attn_fallback);
        attn = (float*)p;
    }

    const int pb_smem = (128 * ZP2 + 16 * ZP) * 4 + 128 * CBP * 4;
    cudaFuncSetAttribute(k_pairbias_tc, cudaFuncAttributeMaxDynamicSharedMemorySize, pb_smem);

    k_detect     <<<1, 256>>>((const unsigned int*)mask);
    k_proj_tc    <<<dim3(48, 8),     256>>>(s, Wq, bq, Wk, bk, Wv, bv, Wg, bg);
    k_pairbias_tc<<<dim3(LC, 8),     256, pb_smem>>>(z, mask, dist, prior, Wz, attn);
    k_qk         <<<dim3(16, 8, 16), 256>>>(attn);
    k_softmax    <<<NH * LC,         128>>>(attn);
    k_av         <<<dim3(16, NH),    128>>>(attn);
    k_out_tc     <<<dim3(12, 8),     256>>>(Wo, bo, Y);
}

// round 14
// speedup vs baseline: 1.0717x; 1.0717x over previous
#include <cuda_runtime.h>
#include <cstdint>

#define LC 1024
#define CS 768
#define NH 16
#define DH 48
#define CP 128

typedef unsigned long long ull;
typedef unsigned int u32;

// ---- scratch (device globals) ----
__device__ float g_Q[LC * CS];
__device__ float g_K[LC * CS];
__device__ float g_V[LC * CS];
__device__ float g_gate[LC * CS];
__device__ float g_ctx[LC * CS];
__device__ float g_attn_fallback[NH * LC * LC];
__device__ int   g_mask_is_u8;

// ---- f32x2 helpers ----
__device__ __forceinline__ ull ffma2(ull a, ull b, ull c) {
    ull d;
    asm("fma.rn.f32x2 %0,%1,%2,%3;" : "=l"(d) : "l"(a), "l"(b), "l"(c));
    return d;
}
__device__ __forceinline__ ull pack2(float lo, float hi) {
    ull r;
    asm("mov.b64 %0,{%1,%2};" : "=l"(r) : "f"(lo), "f"(hi));
    return r;
}
__device__ __forceinline__ void unpack2(ull v, float& lo, float& hi) {
    asm("mov.b64 {%0,%1},%2;" : "=f"(lo), "=f"(hi) : "l"(v));
}

// ---- tf32 mma helpers ----
__device__ __forceinline__ unsigned f2tf(float x) {
    unsigned r;
    asm("cvt.rna.tf32.f32 %0, %1;" : "=r"(r) : "f"(x));
    return r;
}
__device__ __forceinline__ void split_tf32(float x, unsigned& h, unsigned& l) {
    h = f2tf(x);
    l = f2tf(x - __uint_as_float(h));
}
__device__ __forceinline__ void mma_tf32(float* c, const unsigned* a, const unsigned* b) {
    asm("mma.sync.aligned.m16n8k8.row.col.f32.tf32.tf32.f32 "
        "{%0,%1,%2,%3}, {%4,%5,%6,%7}, {%8,%9}, {%0,%1,%2,%3};"
        : "+f"(c[0]), "+f"(c[1]), "+f"(c[2]), "+f"(c[3])
        : "r"(a[0]), "r"(a[1]), "r"(a[2]), "r"(a[3]), "r"(b[0]), "r"(b[1]));
}

// =====================================================================
// K0: mask dtype detector
// =====================================================================
__global__ void k_detect(const unsigned int* __restrict__ m)
{
    __shared__ int s;
    if (threadIdx.x == 0) s = 0;
    __syncthreads();
    int bad = 0;
    for (int i = threadIdx.x; i < 1024; i += blockDim.x)
        if (m[i] > 1u) bad = 1;
    if (bad) atomicOr(&s, 1);
    __syncthreads();
    if (threadIdx.x == 0) g_mask_is_u8 = s;
}

// =====================================================================
// K1: fused projections via tensor cores (tf32x3, inline split)
// =====================================================================
__global__ void __launch_bounds__(256) k_proj_tc(
    const float* __restrict__ S,
    const float* __restrict__ Wq, const float* __restrict__ bq,
    const float* __restrict__ Wk, const float* __restrict__ bk,
    const float* __restrict__ Wv, const float* __restrict__ bv,
    const float* __restrict__ Wg, const float* __restrict__ bg)
{
    __shared__ __align__(16) float As[128 * 36];
    __shared__ __align__(16) float Bs[64 * 36];

    int ntb = blockIdx.x;
    int wi = ntb / 12;
    int n0 = (ntb % 12) * 64;
    int m0 = blockIdx.y * 128;

    const float* W   = wi == 0 ? Wq : wi == 1 ? Wk : wi == 2 ? Wv : Wg;
    const float* bb  = wi == 0 ? bq : wi == 1 ? bk : wi == 2 ? bv : bg;
    float*       dst = wi == 0 ? g_Q : wi == 1 ? g_K : wi == 2 ? g_V : g_gate;

    int t = threadIdx.x;
    int warp = t >> 5, lane = t & 31;
    int wm = warp >> 1, wn = warp & 1;
    int g = lane >> 2, tg = lane & 3;

    float acc[2][4][4] = {};

    for (int k0 = 0; k0 < CS; k0 += 32) {
#pragma unroll
        for (int l = 0; l < 4; l++) {
            int idx = l * 256 + t, row = idx >> 3, q = idx & 7;
            float4 v = *(const float4*)(S + (size_t)(m0 + row) * CS + k0 + q * 4);
            *(float4*)(As + row * 36 + q * 4) = v;
        }
#pragma unroll
        for (int l = 0; l < 2; l++) {
            int idx = l * 256 + t, kk = idx >> 4, q = idx & 15;
            float4 v = *(const float4*)(W + (size_t)(k0 + kk) * CS + n0 + q * 4);
            Bs[(q * 4 + 0) * 36 + kk] = v.x;
            Bs[(q * 4 + 1) * 36 + kk] = v.y;
            Bs[(q * 4 + 2) * 36 + kk] = v.z;
            Bs[(q * 4 + 3) * 36 + kk] = v.w;
        }
        __syncthreads();

#pragma unroll
        for (int ks = 0; ks < 4; ks++) {
            int kb = ks * 8;
            unsigned bh[4][2], bl[4][2];
#pragma unroll
            for (int nt = 0; nt < 4; nt++)
#pragma unroll
                for (int e = 0; e < 2; e++)
                    split_tf32(Bs[(wn * 32 + nt * 8 + g) * 36 + kb + tg + 4 * e],
                               bh[nt][e], bl[nt][e]);
#pragma unroll
            for (int mt = 0; mt < 2; mt++) {
                unsigned ah[4], al[4];
                int r0 = wm * 32 + mt * 16 + g;
                split_tf32(As[r0 * 36 + kb + tg],           ah[0], al[0]);
                split_tf32(As[(r0 + 8) * 36 + kb + tg],     ah[1], al[1]);
                split_tf32(As[r0 * 36 + kb + tg + 4],       ah[2], al[2]);
                split_tf32(As[(r0 + 8) * 36 + kb + tg + 4], ah[3], al[3]);
#pragma unroll
                for (int nt = 0; nt < 4; nt++) {
                    mma_tf32(acc[mt][nt], ah, bh[nt]);
                    mma_tf32(acc[mt][nt], ah, bl[nt]);
                    mma_tf32(acc[mt][nt], al, bh[nt]);
                }
            }
        }
        __syncthreads();
    }

#pragma unroll
    for (int mt = 0; mt < 2; mt++)
#pragma unroll
        for (int nt = 0; nt < 4; nt++) {
            int col = n0 + wn * 32 + nt * 8 + 2 * tg;
            float b0 = bb[col], b1 = bb[col + 1];
            int r = m0 + wm * 32 + mt * 16 + g;
            float v0 = acc[mt][nt][0] + b0, v1 = acc[mt][nt][1] + b1;
            float v2 = acc[mt][nt][2] + b0, v3 = acc[mt][nt][3] + b1;
            if (wi == 3) {
                v0 = 1.f / (1.f + __expf(-v0));
                v1 = 1.f / (1.f + __expf(-v1));
                v2 = 1.f / (1.f + __expf(-v2));
                v3 = 1.f / (1.f + __expf(-v3));
            }
            *(float2*)(dst + (size_t)r * CS + col)       = make_float2(v0, v1);
            *(float2*)(dst + (size_t)(r + 8) * CS + col) = make_float2(v2, v3);
        }
}

// =====================================================================
// K2: pair bias via TC, raw-bit tf32 z, K chunked (2x64), 4 CTAs/SM
// =====================================================================
#define ZP  132
#define ZP2 68
#define CBP 18

__global__ void __launch_bounds__(256) k_pairbias_tc(
    const float* __restrict__ z, const void* __restrict__ maskp,
    const float* __restrict__ dist, const float* __restrict__ prior,
    const float* __restrict__ Wz, float* __restrict__ A)
{
    extern __shared__ __align__(16) u32 smp[];
    u32*   Zs   = smp;                           // 128*68 chunk (raw fp32 bits)
    u32*   Wzs  = smp + 128 * ZP2;               // 16*132 tf32 full K
    float* Cbuf = (float*)(Wzs + 16 * ZP);       // 128*18
    float* tr   = (float*)smp;                   // reuse Zs after mma

    int i = blockIdx.x, jt = blockIdx.y;
    int t = threadIdx.x;
    int warp = t >> 5, lane = t & 31;
    int g = lane >> 2, tg = lane & 3;

#pragma unroll
    for (int l = 0; l < 8; l++) {
        int idx = l * 256 + t;
        int c = idx >> 4, h = idx & 15;
        Wzs[h * ZP + c] = f2tf(Wz[c * 16 + h]);
    }

    float acc[2][4] = {};
    int p0 = warp * 16 + g;

#pragma unroll
    for (int ch = 0; ch < 2; ch++) {
        const uint4* zb = (const uint4*)(z + ((size_t)i * LC + jt * 128) * CP + ch * 64);
#pragma unroll
        for (int l = 0; l < 8; l++) {
            int idx = l * 256 + t;
            int pair = idx >> 4, q = idx & 15;
            *(uint4*)(Zs + pair * ZP2 + q * 4) = zb[pair * 32 + q];
        }
        __syncthreads();

#pragma unroll
        for (int ks = 0; ks < 8; ks++) {
            int kb = ks * 8;
            unsigned a[4];
            a[0] = Zs[p0 * ZP2 + kb + tg];
            a[1] = Zs[(p0 + 8) * ZP2 + kb + tg];
            a[2] = Zs[p0 * ZP2 + kb + tg + 4];
            a[3] = Zs[(p0 + 8) * ZP2 + kb + tg + 4];
#pragma unroll
            for (int nt = 0; nt < 2; nt++) {
                unsigned b[2];
                b[0] = Wzs[(nt * 8 + g) * ZP + ch * 64 + kb + tg];
                b[1] = Wzs[(nt * 8 + g) * ZP + ch * 64 + kb + tg + 4];
                mma_tf32(acc[nt], a, b);
            }
        }
        __syncthreads();
    }

#pragma unroll
    for (int nt = 0; nt < 2; nt++) {
        int h0 = nt * 8 + 2 * tg;
        Cbuf[p0 * CBP + h0]           = acc[nt][0];
        Cbuf[p0 * CBP + h0 + 1]       = acc[nt][1];
        Cbuf[(p0 + 8) * CBP + h0]     = acc[nt][2];
        Cbuf[(p0 + 8) * CBP + h0 + 1] = acc[nt][3];
    }
    __syncthreads();

    float v16[16];
    if (t < 128) {
        int j = jt * 128 + t;
        int ij = i * LC + j;
        const float4* dv = (const float4*)(dist + (size_t)ij * 16);
        float4 d0 = dv[0], d1 = dv[1], d2 = dv[2], d3 = dv[3];
        float db[16] = {d0.x, d0.y, d0.z, d0.w, d1.x, d1.y, d1.z, d1.w,
                        d2.x, d2.y, d2.z, d2.w, d3.x, d3.y, d3.z, d3.w};
        float pr = prior[ij];
        bool mv;
        if (g_mask_is_u8)
            mv = ((const unsigned char*)maskp)[ij] != 0;
        else
            mv = ((const int*)maskp)[ij] != 0;
#pragma unroll
        for (int hh = 0; hh < 16; hh++) {
            float vv = Cbuf[t * CBP + hh] + db[hh] + pr;
            v16[hh] = mv ? vv : -1e30f;
        }
    }
    __syncthreads();
    if (t < 128) {
#pragma unroll
        for (int hh = 0; hh < 16; hh++) tr[hh * 128 + t] = v16[hh];
    }
    __syncthreads();
#pragma unroll
    for (int l = 0; l < 8; l++) {
        int idx = l * 256 + t;
        int hh = idx >> 7, col = idx & 127;
        A[((size_t)hh * LC + i) * LC + jt * 128 + col] = tr[hh * 128 + col];
    }
}

// =====================================================================
// K3: logits += scale*QK^T, k-paired f32x2 (RMW)
// =====================================================================
#define QK_SCALE 0.14433756729740643f   // 1/sqrt(48)

__global__ void __launch_bounds__(256, 2) k_qk(float* __restrict__ A)
{
    __shared__ __align__(16) ull Asp[24 * 128];
    __shared__ __align__(16) ull Bsp[24 * 64];

    int jb = blockIdx.x;
    int j0 = jb * 64, i0 = blockIdx.y * 128, h = blockIdx.z;
    int t = threadIdx.x, tx = t & 15, ty = t >> 4;

#pragma unroll
    for (int l = 0; l < 6; l++) {
        int idx = l * 256 + t;
        int row = idx & 127, q = idx >> 7;
        float4 v = *(const float4*)(g_Q + (size_t)(i0 + row) * CS + h * DH + q * 4);
        Asp[(2 * q) * 128 + row]     = pack2(v.x * QK_SCALE, v.y * QK_SCALE);
        Asp[(2 * q + 1) * 128 + row] = pack2(v.z * QK_SCALE, v.w * QK_SCALE);
    }
#pragma unroll
    for (int l = 0; l < 3; l++) {
        int idx = l * 256 + t;
        int row = idx & 63, q = idx >> 6;
        float4 v = *(const float4*)(g_K + (size_t)(j0 + row) * CS + h * DH + q * 4);
        Bsp[(2 * q) * 64 + row]     = pack2(v.x, v.y);
        Bsp[(2 * q + 1) * 64 + row] = pack2(v.z, v.w);
    }
    __syncthreads();

    ull acc[8][4];
#pragma unroll
    for (int r = 0; r < 8; r++)
#pragma unroll
        for (int j = 0; j < 4; j++) acc[r][j] = 0ull;

#pragma unroll 6
    for (int kp = 0; kp < 24; kp++) {
        const ulonglong2* Ap2 = (const ulonglong2*)(Asp + kp * 128);
        const ull* Bp = Bsp + kp * 64;
        ull b[4];
#pragma unroll
        for (int j = 0; j < 4; j++) b[j] = Bp[tx + 16 * j];
#pragma unroll
        for (int p = 0; p < 4; p++) {
            ulonglong2 av = Ap2[ty * 4 + p];
#pragma unroll
            for (int j = 0; j < 4; j++) {
                acc[2 * p][j]     = ffma2(av.x, b[j], acc[2 * p][j]);
                acc[2 * p + 1][j] = ffma2(av.y, b[j], acc[2 * p + 1][j]);
            }
        }
    }

#pragma unroll
    for (int r = 0; r < 8; r++) {
        int row = i0 + ty * 8 + r;
        float* C = A + ((size_t)h * LC + row) * LC + j0;
#pragma unroll
        for (int j = 0; j < 4; j++) {
            float lo, hi;
            unpack2(acc[r][j], lo, hi);
            C[tx + 16 * j] += lo + hi;
        }
    }
}

// =====================================================================
// K3b: rowwise softmax in place (pure __expf - R12 proven version)
// =====================================================================
__global__ void __launch_bounds__(128) k_softmax(float* __restrict__ A)
{
    size_t r = blockIdx.x;
    float* row = A + r * LC;
    int t = threadIdx.x;
    float4 v0 = ((float4*)row)[2 * t], v1 = ((float4*)row)[2 * t + 1];

    float mx = fmaxf(fmaxf(fmaxf(v0.x, v0.y), fmaxf(v0.z, v0.w)),
                     fmaxf(fmaxf(v1.x, v1.y), fmaxf(v1.z, v1.w)));
#pragma unroll
    for (int o = 16; o; o >>= 1) mx = fmaxf(mx, __shfl_xor_sync(0xffffffffu, mx, o));
    __shared__ float sm[4], ss[4];
    if ((t & 31) == 0) sm[t >> 5] = mx;
    __syncthreads();
    mx = fmaxf(fmaxf(sm[0], sm[1]), fmaxf(sm[2], sm[3]));

    v0.x = __expf(v0.x - mx); v0.y = __expf(v0.y - mx);
    v0.z = __expf(v0.z - mx); v0.w = __expf(v0.w - mx);
    v1.x = __expf(v1.x - mx); v1.y = __expf(v1.y - mx);
    v1.z = __expf(v1.z - mx); v1.w = __expf(v1.w - mx);
    float s = v0.x + v0.y + v0.z + v0.w + v1.x + v1.y + v1.z + v1.w;
#pragma unroll
    for (int o = 16; o; o >>= 1) s += __shfl_xor_sync(0xffffffffu, s, o);
    if ((t & 31) == 0) ss[t >> 5] = s;
    __syncthreads();
    s = ss[0] + ss[1] + ss[2] + ss[3];

    float inv = 1.f / s;
    v0.x *= inv; v0.y *= inv; v0.z *= inv; v0.w *= inv;
    v1.x *= inv; v1.y *= inv; v1.z *= inv; v1.w *= inv;
    ((float4*)row)[2 * t] = v0;
    ((float4*)row)[2 * t + 1] = v1;
}

// =====================================================================
// K4: ctx = attn @ V per head. tile 64 rows, 128 thr, micro 8x3 (f32x2)
// =====================================================================
__global__ void __launch_bounds__(128) k_av(const float* __restrict__ A)
{
    __shared__ __align__(16) float  As[32 * 64];
    __shared__ __align__(16) float2 Vs[32 * 48];

    int i0 = blockIdx.x * 64, h = blockIdx.y;
    int t = threadIdx.x, tx = t & 15, ty = t >> 4;

    ull acc[4][3];
#pragma unroll
    for (int p = 0; p < 4; p++)
#pragma unroll
        for (int c = 0; c < 3; c++) acc[p][c] = 0ull;

    for (int j0 = 0; j0 < LC; j0 += 32) {
#pragma unroll
        for (int l = 0; l < 4; l++) {
            int idx = l * 128 + t, row = idx >> 3, q = idx & 7;
            float4 v = *(const float4*)(A + ((size_t)h * LC + i0 + row) * LC + j0 + q * 4);
            As[(q * 4 + 0) * 64 + row] = v.x;
            As[(q * 4 + 1) * 64 + row] = v.y;
            As[(q * 4 + 2) * 64 + row] = v.z;
            As[(q * 4 + 3) * 64 + row] = v.w;
        }
#pragma unroll
        for (int l = 0; l < 3; l++) {
            int idx = l * 128 + t;
            int jj = idx / 12, q = idx - jj * 12;
            float4 v = *(const float4*)(g_V + (size_t)(j0 + jj) * CS + h * DH + q * 4);
            Vs[jj * 48 + q * 4 + 0] = make_float2(v.x, v.x);
            Vs[jj * 48 + q * 4 + 1] = make_float2(v.y, v.y);
            Vs[jj * 48 + q * 4 + 2] = make_float2(v.z, v.z);
            Vs[jj * 48 + q * 4 + 3] = make_float2(v.w, v.w);
        }
        __syncthreads();
#pragma unroll
        for (int kk = 0; kk < 32; kk++) {
            const ull* Ap = (const ull*)(As + kk * 64);
            const ull* Vp = (const ull*)(Vs + kk * 48);
            ull a2[4], b2[3];
#pragma unroll
            for (int p = 0; p < 4; p++) a2[p] = Ap[ty * 4 + p];
#pragma unroll
            for (int c = 0; c < 3; c++) b2[c] = Vp[tx * 3 + c];
#pragma unroll
            for (int p = 0; p < 4; p++)
#pragma unroll
                for (int c = 0; c < 3; c++) acc[p][c] = ffma2(a2[p], b2[c], acc[p][c]);
        }
        __syncthreads();
    }

#pragma unroll
    for (int p = 0; p < 4; p++) {
        int r = i0 + ty * 8 + 2 * p;
#pragma unroll
        for (int c = 0; c < 3; c++) {
            float lo, hi;
            unpack2(acc[p][c], lo, hi);
            g_ctx[(size_t)r * CS + h * DH + tx * 3 + c]       = lo;
            g_ctx[(size_t)(r + 1) * CS + h * DH + tx * 3 + c] = hi;
        }
    }
}

// =====================================================================
// K5: y = gate * (ctx @ Wo + bo) via tensor cores (tf32x3, inline split)
// =====================================================================
__global__ void __launch_bounds__(256) k_out_tc(
    const float* __restrict__ Wo, const float* __restrict__ bo, float* __restrict__ Y)
{
    __shared__ __align__(16) float As[128 * 36];
    __shared__ __align__(16) float Bs[64 * 36];

    int n0 = blockIdx.x * 64;
    int m0 = blockIdx.y * 128;

    int t = threadIdx.x;
    int warp = t >> 5, lane = t & 31;
    int wm = warp >> 1, wn = warp & 1;
    int g = lane >> 2, tg = lane & 3;

    float acc[2][4][4] = {};

    for (int k0 = 0; k0 < CS; k0 += 32) {
#pragma unroll
        for (int l = 0; l < 4; l++) {
            int idx = l * 256 + t, row = idx >> 3, q = idx & 7;
            float4 v = *(const float4*)(g_ctx + (size_t)(m0 + row) * CS + k0 + q * 4);
            *(float4*)(As + row * 36 + q * 4) = v;
        }
#pragma unroll
        for (int l = 0; l < 2; l++) {
            int idx = l * 256 + t, kk = idx >> 4, q = idx & 15;
            float4 v = *(const float4*)(Wo + (size_t)(k0 + kk) * CS + n0 + q * 4);
            Bs[(q * 4 + 0) * 36 + kk] = v.x;
            Bs[(q * 4 + 1) * 36 + kk] = v.y;
            Bs[(q * 4 + 2) * 36 + kk] = v.z;
            Bs[(q * 4 + 3) * 36 + kk] = v.w;
        }
        __syncthreads();

#pragma unroll
        for (int ks = 0; ks < 4; ks++) {
            int kb = ks * 8;
            unsigned bh[4][2], bl[4][2];
#pragma unroll
            for (int nt = 0; nt < 4; nt++)
#pragma unroll
                for (int e = 0; e < 2; e++)
                    split_tf32(Bs[(wn * 32 + nt * 8 + g) * 36 + kb + tg + 4 * e],
                               bh[nt][e], bl[nt][e]);
#pragma unroll
            for (int mt = 0; mt < 2; mt++) {
                unsigned ah[4], al[4];
                int r0 = wm * 32 + mt * 16 + g;
                split_tf32(As[r0 * 36 + kb + tg],           ah[0], al[0]);
                split_tf32(As[(r0 + 8) * 36 + kb + tg],     ah[1], al[1]);
                split_tf32(As[r0 * 36 + kb + tg + 4],       ah[2], al[2]);
                split_tf32(As[(r0 + 8) * 36 + kb + tg + 4], ah[3], al[3]);
#pragma unroll
                for (int nt = 0; nt < 4; nt++) {
                    mma_tf32(acc[mt][nt], ah, bh[nt]);
                    mma_tf32(acc[mt][nt], ah, bl[nt]);
                    mma_tf32(acc[mt][nt], al, bh[nt]);
                }
            }
        }
        __syncthreads();
    }

#pragma unroll
    for (int mt = 0; mt < 2; mt++)
#pragma unroll
        for (int nt = 0; nt < 4; nt++) {
            int col = n0 + wn * 32 + nt * 8 + 2 * tg;
            float b0 = bo[col], b1 = bo[col + 1];
            int r = m0 + wm * 32 + mt * 16 + g;
            float2 ga = *(const float2*)(g_gate + (size_t)r * CS + col);
            float2 gb = *(const float2*)(g_gate + (size_t)(r + 8) * CS + col);
            *(float2*)(Y + (size_t)r * CS + col) =
                make_float2((acc[mt][nt][0] + b0) * ga.x, (acc[mt][nt][1] + b1) * ga.y);
            *(float2*)(Y + (size_t)(r + 8) * CS + col) =
                make_float2((acc[mt][nt][2] + b0) * gb.x, (acc[mt][nt][3] + b1) * gb.y);
        }
}

// =====================================================================
extern "C" void kernel_launch(void* const* d_in, const int* in_sizes, int n_in,
                              void* d_out, int out_size)
{
    const float* s     = (const float*)d_in[0];
    const float* z     = (const float*)d_in[1];
    const void*  mask  = d_in[2];
    const float* dist  = (const float*)d_in[3];
    const float* prior = (const float*)d_in[4];
    const float* Wq = (const float*)d_in[5];  const float* bq = (const float*)d_in[6];
    const float* Wk = (const float*)d_in[7];  const float* bk = (const float*)d_in[8];
    const float* Wv = (const float*)d_in[9];  const float* bv = (const float*)d_in[10];
    const float* Wz = (const float*)d_in[11];
    const float* Wo = (const float*)d_in[12]; const float* bo = (const float*)d_in[13];
    const float* Wg = (const float*)d_in[14]; const float* bg = (const float*)d_in[15];

    float* Y = (float*)d_out;
    float* attn;
    if (out_size >= LC * CS + NH * LC * LC) {
        attn = (float*)d_out + LC * CS;
    } else {
        void* p = nullptr;
        cudaGetSymbolAddress(&p, g_attn_fallback);
        attn = (float*)p;
    }

    const int pb_smem = (128 * ZP2 + 16 * ZP) * 4 + 128 * CBP * 4;
    cudaFuncSetAttribute(k_pairbias_tc, cudaFuncAttributeMaxDynamicSharedMemorySize, pb_smem);

    // side stream + events: created once on the first (uncaptured) call,
    // reused on every call -> identical work per call, nothing created
    // during graph capture.
    static cudaStream_t s2 = nullptr;
    static cudaEvent_t  evFork = nullptr, evJoin = nullptr;
    if (s2 == nullptr) {
        cudaStreamCreateWithFlags(&s2, cudaStreamNonBlocking);
        cudaEventCreateWithFlags(&evFork, cudaEventDisableTiming);
        cudaEventCreateWithFlags(&evJoin, cudaEventDisableTiming);
    }

    // fork: pairbias branch (detect -> pairbias) on s2, proj on main stream
    cudaEventRecord(evFork, 0);
    cudaStreamWaitEvent(s2, evFork, 0);

    k_detect     <<<1, 256, 0, s2>>>((const unsigned int*)mask);
    k_pairbias_tc<<<dim3(LC, 8), 256, pb_smem, s2>>>(z, mask, dist, prior, Wz, attn);

    k_proj_tc    <<<dim3(48, 8), 256>>>(s, Wq, bq, Wk, bk, Wv, bv, Wg, bg);

    // join: qk needs both proj (Q,K) and pairbias (A base)
    cudaEventRecord(evJoin, s2);
    cudaStreamWaitEvent(0, evJoin, 0);

    k_qk      <<<dim3(16, 8, 16), 256>>>(attn);
    k_softmax <<<NH * LC,         128>>>(attn);
    k_av      <<<dim3(16, NH),    128>>>(attn);
    k_out_tc  <<<dim3(12, 8),     256>>>(Wo, bo, Y);
}